// round 17
// baseline (speedup 1.0000x reference)
#include <cuda_runtime.h>
#include <cuda_bf16.h>
#include <cstdint>

#define B 2
#define N 16384
#define M 4096
#define E 32
#define C 64
#define S 32
#define NCH 96
#define R2 0.01f
#define TP 37
#define GC 10
#define NCELL (GC * GC * GC)
#define CAP 128

// ---------------- scratch ----------------------------------------------------
__device__ float4 g_xyz4[B * N];                 // {x,y,z,norm} index order
__device__ __align__(16) float g_feat_t[(size_t)B * N * C];
__device__ int    g_cnt[B * NCELL];              // zero-init; re-zeroed by query_gather
__device__ int    g_fill[B * NCELL];             // zero-init; re-zeroed by query_gather
__device__ int    g_cellStart[B * (NCELL + 1)];
__device__ float4 g_ptmp[B * N];                 // cell-bucketed {x,y,z,idx}

// ---- frozen fp formulas (bit-exact vs XLA; do not touch) --------------------
__device__ __forceinline__ float norm3_nofma(float x, float y, float z) {
    return __fadd_rn(__fadd_rn(__fmul_rn(x, x), __fmul_rn(y, y)),
                     __fmul_rn(z, z));
}
__device__ __forceinline__ float dot3_fma(float ax, float ay, float az,
                                          float bx, float by, float bz) {
    return __fmaf_rn(az, bz, __fmaf_rn(ay, by, __fmul_rn(ax, bx)));
}
__device__ __forceinline__ int cell_of(float x, float y, float z) {
    int cx = min((int)(x * 10.0f), GC - 1);
    int cy = min((int)(y * 10.0f), GC - 1);
    int cz = min((int)(z * 10.0f), GC - 1);
    return (cz * GC + cy) * GC + cx;
}

// ------ K1: fused pack xyz + grid count | feature transpose ------------------
__global__ __launch_bounds__(256) void prep_kernel(
        const float* __restrict__ xyz, const float* __restrict__ f) {
    if (blockIdx.x < 128) {
        int i = blockIdx.x * 256 + threadIdx.x;      // < B*N
        float x = xyz[3 * i + 0], y = xyz[3 * i + 1], z = xyz[3 * i + 2];
        g_xyz4[i] = make_float4(x, y, z, norm3_nofma(x, y, z));
        int b = i >> 14;
        atomicAdd(&g_cnt[b * NCELL + cell_of(x, y, z)], 1);
    } else {
        __shared__ float t[32][33];
        int bi = blockIdx.x - 128;
        int n0 = (bi & 511) * 32;
        int c0 = ((bi >> 9) & 1) * 32;
        int b  = bi >> 10;
        int tx = threadIdx.x & 31, ty = threadIdx.x >> 5;
#pragma unroll
        for (int i = 0; i < 32; i += 8)
            t[ty + i][tx] = f[((size_t)(b * C + c0 + ty + i)) * N + n0 + tx];
        __syncthreads();
#pragma unroll
        for (int i = 0; i < 32; i += 8)
            g_feat_t[((size_t)b * N + n0 + ty + i) * C + c0 + tx] = t[tx][ty + i];
    }
}

// ------ K2: fused in-block scan + scatter ------------------------------------
__global__ __launch_bounds__(256) void scan_scatter_kernel() {
    __shared__ int sstart[NCELL + 4];
    __shared__ int ws[8];
    int tid = threadIdx.x;
    int b = blockIdx.x >> 6;                 // 64 blocks per batch

    int c0 = tid * 4;
    int v[4];
    int sum = 0;
#pragma unroll
    for (int k = 0; k < 4; k++) {
        int c = c0 + k;
        v[k] = (c < NCELL) ? g_cnt[b * NCELL + c] : 0;
        sum += v[k];
    }
    int lane = tid & 31, wid = tid >> 5;
    int x = sum;
#pragma unroll
    for (int o = 1; o < 32; o <<= 1) {
        int y = __shfl_up_sync(0xFFFFFFFFu, x, o);
        if (lane >= o) x += y;
    }
    if (lane == 31) ws[wid] = x;
    __syncthreads();
    if (wid == 0) {
        int z = (lane < 8) ? ws[lane] : 0;
#pragma unroll
        for (int o = 1; o < 8; o <<= 1) {
            int y = __shfl_up_sync(0xFFFFFFFFu, z, o);
            if (lane >= o) z += y;
        }
        if (lane < 8) ws[lane] = z;
    }
    __syncthreads();
    int excl = x - sum + (wid ? ws[wid - 1] : 0);
#pragma unroll
    for (int k = 0; k < 4; k++) {
        int c = c0 + k;
        if (c <= NCELL) sstart[c] = excl;
        excl += v[k];
    }
    __syncthreads();

    if ((blockIdx.x & 63) == 0)
        for (int t = tid; t <= NCELL; t += 256)
            g_cellStart[b * (NCELL + 1) + t] = sstart[t];

    int i = blockIdx.x * 256 + tid;          // < B*N
    float4 q = g_xyz4[i];
    int c = cell_of(q.x, q.y, q.z);
    int pos = sstart[c] + atomicAdd(&g_fill[b * NCELL + c], 1);
    g_ptmp[b * N + pos] = make_float4(q.x, q.y, q.z, __int_as_float(i & (N - 1)));
}

// ---------------- fallback: ordered linear scan (proven correct) -------------
__device__ __noinline__ void linear_scan_center(
        float nx, float ny, float nz, float sn, int b, int* ob, int lane) {
    const float4* __restrict__ P = g_xyz4 + b * N;
    const unsigned FULL = 0xFFFFFFFFu;
    const unsigned lt = (1u << lane) - 1u;
    int cnt = 0, first = 0;
    for (int j0 = 0; j0 < N && cnt < S; j0 += 32) {
        float4 p = P[j0 + lane];
        int j = j0 + lane;
        float dot = dot3_fma(nx, ny, nz, p.x, p.y, p.z);
        float d2  = __fmaf_rn(-2.0f, dot, __fadd_rn(sn, p.w));
        bool hit  = d2 < R2;
        unsigned mask = __ballot_sync(FULL, hit);
        if (mask) {
            int pos = cnt + __popc(mask & lt);
            if (hit && pos < S) ob[pos] = j;
            if (cnt == 0) first = __shfl_sync(FULL, j, __ffs(mask) - 1);
            cnt += __popc(mask);
        }
    }
    if (lane >= cnt) ob[lane] = first;
}

// ---- generalized warp bitonic sort: NR*32 keys, NR regs/lane, ascending -----
template <int NR>
__device__ __forceinline__ void bitonic_sort_warp(int (&v)[NR], int lane) {
    const unsigned FULL = 0xFFFFFFFFu;
#pragma unroll
    for (int k = 2; k <= NR * 32; k <<= 1) {
#pragma unroll
        for (int j = NR * 16; j > 0; j >>= 1) {
            if (j >= k) continue;
            if (j >= 32) {               // cross-register (k >= 64 here)
                int jr = j >> 5;
#pragma unroll
                for (int r = 0; r < NR; r++) {
                    if ((r & jr) == 0) {
                        int r2 = r | jr;
                        bool up = (((r * 32) & k) == 0);
                        int a = v[r], c = v[r2];
                        int lo = min(a, c), hi = max(a, c);
                        v[r]  = up ? lo : hi;
                        v[r2] = up ? hi : lo;
                    }
                }
            } else {
#pragma unroll
                for (int r = 0; r < NR; r++) {
                    int other = __shfl_xor_sync(FULL, v[r], j);
                    bool up = (((r * 32 + lane) & k) == 0);
                    bool lower = ((lane & j) == 0);
                    v[r] = (up == lower) ? min(v[r], other) : max(v[r], other);
                }
            }
        }
    }
}

template <int NR>
__device__ __forceinline__ void sort_emit(const int* bufw, int cnt, int lane,
                                          int* ob) {
    int v[NR];
#pragma unroll
    for (int r = 0; r < NR; r++) {
        int t = r * 32 + lane;
        v[r] = (t < cnt) ? bufw[t] : 0x7FFFFFFF;
    }
    bitonic_sort_warp<NR>(v, lane);
    int my = v[0];
    int first = __shfl_sync(0xFFFFFFFFu, my, 0);
    if (cnt == 0) first = 0;
    ob[lane] = (lane < cnt) ? my : first;
}

// ------ K3: fused ball query (warp/center) + gather (double-buffered) --------
__global__ __launch_bounds__(256) void query_gather_kernel(
        const float* __restrict__ new_xyz,
        const float* __restrict__ xyz_embed,
        const float* __restrict__ new_xyz_embed,
        float* __restrict__ out) {
    __shared__ int   buf[8][CAP];
    __shared__ int   sidx[8][S];
    __shared__ float tile[NCH * TP];

    int w    = threadIdx.x >> 5;
    int lane = threadIdx.x & 31;
    int tid  = threadIdx.x;
    int gw   = blockIdx.x * 8 + w;        // this warp's center
    const unsigned FULL = 0xFFFFFFFFu;
    const unsigned lt   = (1u << lane) - 1u;

    // re-zero grid counters for the next launch (nothing reads them here)
    if (blockIdx.x < 8) {
        int z = blockIdx.x * 256 + tid;
        if (z < B * NCELL) { g_cnt[z] = 0; g_fill[z] = 0; }
    }

    // ================= query phase (warp per center) =================
    {
        int b = gw >> 12;
        const float nx = new_xyz[3 * gw + 0];
        const float ny = new_xyz[3 * gw + 1];
        const float nz = new_xyz[3 * gw + 2];
        const float sn = norm3_nofma(nx, ny, nz);

        const float4* __restrict__ P = g_ptmp + b * N;
        const int* __restrict__ cs = g_cellStart + b * (NCELL + 1);

        int z0 = max(0, (int)floorf((nz - 0.1001f) * 10.f));
        int z1 = min(GC - 1, (int)floorf((nz + 0.1001f) * 10.f));
        int y0 = max(0, (int)floorf((ny - 0.1001f) * 10.f));
        int y1 = min(GC - 1, (int)floorf((ny + 0.1001f) * 10.f));

        int cnt = 0;
        for (int gz = z0; gz <= z1; gz++) {
            float dz = fmaxf(fmaxf(0.1f * gz - nz, nz - 0.1f * (gz + 1)), 0.f);
            for (int gy = y0; gy <= y1; gy++) {
                float dy = fmaxf(fmaxf(0.1f * gy - ny, ny - 0.1f * (gy + 1)), 0.f);
                float rem = (R2 + 2e-4f) - __fmaf_rn(dy, dy, dz * dz);
                if (rem <= 0.f) continue;
                float hwf = sqrtf(rem) + 1e-4f;
                int xa = max(0, (int)floorf((nx - hwf) * 10.f));
                int xb = min(GC - 1, (int)floorf((nx + hwf) * 10.f));
                if (xa > xb) continue;
                int base = (gz * GC + gy) * GC;
                int sS = cs[base + xa];
                int sE = cs[base + xb + 1];
                for (int p0 = sS; p0 < sE; p0 += 32) {
                    int pi = p0 + lane;
                    bool valid = pi < sE;
                    float4 pt = valid ? P[pi] : make_float4(9.f, 9.f, 9.f, 0.f);
                    float sp  = norm3_nofma(pt.x, pt.y, pt.z);
                    float dot = dot3_fma(nx, ny, nz, pt.x, pt.y, pt.z);
                    float d2  = __fmaf_rn(-2.0f, dot, __fadd_rn(sn, sp));
                    bool hit  = valid && (d2 < R2);
                    unsigned mask = __ballot_sync(FULL, hit);
                    if (mask) {
                        int pos = cnt + __popc(mask & lt);
                        if (hit && pos < CAP) buf[w][pos] = __float_as_int(pt.w);
                        cnt += __popc(mask);
                    }
                }
            }
        }
        __syncwarp();

        if (cnt > CAP) {                 // astronomically rare: proven fallback
            linear_scan_center(nx, ny, nz, sn, b, sidx[w], lane);
        } else if (cnt <= 32) {
            sort_emit<1>(buf[w], cnt, lane, sidx[w]);
        } else if (cnt <= 64) {
            sort_emit<2>(buf[w], cnt, lane, sidx[w]);
        } else {
            sort_emit<4>(buf[w], cnt, lane, sidx[w]);
        }
    }
    __syncthreads();

    // ======= gather phase: register double-buffered over 8 centers ==========
    const float4* __restrict__ xe4 = (const float4*)xyz_embed;
    const float4* __restrict__ ne4 = (const float4*)new_xyz_embed;
    const float4* __restrict__ ft4 = (const float4*)g_feat_t;
    float4* __restrict__ out4 = (float4*)out;

    const int sA = tid >> 3, qA = tid & 7;    // embed: point sA, float4 qA
    const int sB = tid >> 4, qB = tid & 15;   // feat: points sB and sB+16, float4 qB

    float4 ev, cv, f0, f1;
    {   // prologue: load center c8=0
        int center = blockIdx.x * 8;
        int b = center >> 12;
        int p  = sidx[0][sA];
        ev = xe4[((size_t)b * N + p) * (E / 4) + qA];
        cv = ne4[(size_t)center * (E / 4) + qA];
        int p0 = sidx[0][sB];
        f0 = ft4[((size_t)b * N + p0) * (C / 4) + qB];
        int p1 = sidx[0][sB + 16];
        f1 = ft4[((size_t)b * N + p1) * (C / 4) + qB];
    }

#pragma unroll 1
    for (int c8 = 0; c8 < 8; c8++) {
        int center = blockIdx.x * 8 + c8;
        int b = center >> 12;
        int m = center & (M - 1);

        // STS current center's registers into transposed tile
        {
            int ch = 4 * qA;
            tile[(ch + 0) * TP + sA] = ev.x - cv.x;
            tile[(ch + 1) * TP + sA] = ev.y - cv.y;
            tile[(ch + 2) * TP + sA] = ev.z - cv.z;
            tile[(ch + 3) * TP + sA] = ev.w - cv.w;
            int cf = E + 4 * qB;
            tile[(cf + 0) * TP + sB] = f0.x;
            tile[(cf + 1) * TP + sB] = f0.y;
            tile[(cf + 2) * TP + sB] = f0.z;
            tile[(cf + 3) * TP + sB] = f0.w;
            tile[(cf + 0) * TP + sB + 16] = f1.x;
            tile[(cf + 1) * TP + sB + 16] = f1.y;
            tile[(cf + 2) * TP + sB + 16] = f1.z;
            tile[(cf + 3) * TP + sB + 16] = f1.w;
        }
        // prefetch next center (LDG latency overlaps barrier + write phase)
        if (c8 < 7) {
            int nc = center + 1;
            int nb = nc >> 12;
            int p  = sidx[c8 + 1][sA];
            ev = xe4[((size_t)nb * N + p) * (E / 4) + qA];
            cv = ne4[(size_t)nc * (E / 4) + qA];
            int p0 = sidx[c8 + 1][sB];
            f0 = ft4[((size_t)nb * N + p0) * (C / 4) + qB];
            int p1 = sidx[c8 + 1][sB + 16];
            f1 = ft4[((size_t)nb * N + p1) * (C / 4) + qB];
        }
        __syncthreads();

        // coalesced channel-row writes
#pragma unroll
        for (int t = tid; t < NCH * (S / 4); t += 256) {
            int ch = t >> 3;
            int s4 = t & 7;
            const float* r = tile + ch * TP + 4 * s4;
            out4[(((size_t)b * NCH + ch) * M + m) * (S / 4) + s4] =
                make_float4(r[0], r[1], r[2], r[3]);
        }
        __syncthreads();                 // tile reused next iteration
    }
}

// ---------------- launch -----------------------------------------------------
extern "C" void kernel_launch(void* const* d_in, const int* in_sizes, int n_in,
                              void* d_out, int out_size) {
    const float* xyz           = (const float*)d_in[0];
    const float* xyz_embed     = (const float*)d_in[1];
    const float* new_xyz       = (const float*)d_in[2];
    const float* new_xyz_embed = (const float*)d_in[3];
    const float* features      = (const float*)d_in[4];
    float* out = (float*)d_out;

    prep_kernel<<<128 + 2048, 256>>>(xyz, features);
    scan_scatter_kernel<<<128, 256>>>();
    query_gather_kernel<<<B * M / 8, 256>>>(new_xyz, xyz_embed, new_xyz_embed, out);
}